// round 13
// baseline (speedup 1.0000x reference)
#include <cuda_runtime.h>
#include <cuda_bf16.h>
#include <cstdint>

#define D 128
#define MAXN 100000
#define MAXN_AL 100032               // padded to TM multiple
#define MAXE 1600000
#define PADK 136                     // padded bf16 row stride
#define ROW_U32 (PADK / 2)           // 68 u32 per bf16 row
#define W_IMG_U32 (128 * PADK / 2)   // 8704 u32 per W image
#define TM 64                        // GEMM CTA row tile

// ---------------- scratch (static device mem) ------------------------------
__device__ unsigned g_Whi[W_IMG_U32];
__device__ unsigned g_Wlo[W_IMG_U32];
__device__ unsigned g_Ahi[MAXN_AL * ROW_U32];   // zero-init (.bss)
__device__ unsigned g_Alo[MAXN_AL * ROW_U32];
__device__ int g_cnt[MAXN];
__device__ int g_off[MAXN + 1];
__device__ int g_csr[MAXE];
__device__ int g_blk[256];

__device__ __forceinline__ unsigned pack_bf16x2(__nv_bfloat16 a, __nv_bfloat16 b) {
    return ((unsigned)*(unsigned short*)&a) | ((unsigned)*(unsigned short*)&b << 16);
}

// ---------------------------------------------------------------------------
// init: W -> bf16 hi/lo images (blocks 0..31) + zero g_cnt (blocks 32..)
// ---------------------------------------------------------------------------
__global__ void k_init(const float* __restrict__ W, int n) {
    int b = blockIdx.x, t = threadIdx.x;
    if (b < 32) {
        int row = b * 4 + (t >> 6);
        int k = (t & 63) * 2;
        float f0 = W[row * D + k], f1 = W[row * D + k + 1];
        __nv_bfloat16 h0 = __float2bfloat16(f0);
        __nv_bfloat16 h1 = __float2bfloat16(f1);
        __nv_bfloat16 l0 = __float2bfloat16(f0 - __bfloat162float(h0));
        __nv_bfloat16 l1 = __float2bfloat16(f1 - __bfloat162float(h1));
        unsigned idx = (unsigned)(row * PADK + k) / 2;
        g_Whi[idx] = pack_bf16x2(h0, h1);
        g_Wlo[idx] = pack_bf16x2(l0, l1);
    } else {
        int i = (b - 32) * 256 + t;
        if (i < n) g_cnt[i] = 0;
    }
}

// ---------------------------------------------------------------------------
// histogram: int4-vectorized, 4 independent atomics per thread (MLP=4)
// ---------------------------------------------------------------------------
__global__ void k_hist(const int* __restrict__ dst, int E) {
    int gid = blockIdx.x * blockDim.x + threadIdx.x;
    int E4 = E >> 2;
    if (gid < E4) {
        int4 d4 = __ldg((const int4*)dst + gid);
        atomicAdd(&g_cnt[d4.x], 1);
        atomicAdd(&g_cnt[d4.y], 1);
        atomicAdd(&g_cnt[d4.z], 1);
        atomicAdd(&g_cnt[d4.w], 1);
    }
    if (gid == 0) {
        for (int e = E4 * 4; e < E; e++) atomicAdd(&g_cnt[dst[e]], 1);
    }
}

// ---------------------------------------------------------------------------
// 3-phase exclusive scan (verified)
// ---------------------------------------------------------------------------
__global__ void k_scan1(int n) {
    __shared__ int wsum[8];
    int b = blockIdx.x, t = threadIdx.x;
    int base = b * 1024 + t * 4;
    int v0 = (base + 0 < n) ? g_cnt[base + 0] : 0;
    int v1 = (base + 1 < n) ? g_cnt[base + 1] : 0;
    int v2 = (base + 2 < n) ? g_cnt[base + 2] : 0;
    int v3 = (base + 3 < n) ? g_cnt[base + 3] : 0;
    int s = v0 + v1 + v2 + v3;

    int lane = t & 31, w = t >> 5;
    int inc = s;
#pragma unroll
    for (int o = 1; o < 32; o <<= 1) {
        int x = __shfl_up_sync(0xffffffffu, inc, o);
        if (lane >= o) inc += x;
    }
    if (lane == 31) wsum[w] = inc;
    __syncthreads();
    if (t == 0) {
        int run = 0;
#pragma unroll
        for (int i = 0; i < 8; i++) { int tmp = wsum[i]; wsum[i] = run; run += tmp; }
        g_blk[b] = run;
    }
    __syncthreads();
    int excl = wsum[w] + inc - s;
    if (base + 0 < n) g_off[base + 0] = excl;
    if (base + 1 < n) g_off[base + 1] = excl + v0;
    if (base + 2 < n) g_off[base + 2] = excl + v0 + v1;
    if (base + 3 < n) g_off[base + 3] = excl + v0 + v1 + v2;
}

__global__ void k_scan2(int nb) {
    __shared__ int s[256];
    int t = threadIdx.x;
    s[t] = (t < nb) ? g_blk[t] : 0;
    __syncthreads();
    if (t == 0) {
        int run = 0;
        for (int i = 0; i < nb; i++) { int tmp = s[i]; s[i] = run; run += tmp; }
    }
    __syncthreads();
    if (t < nb) g_blk[t] = s[t];
}

__global__ void k_scan3(int n, int E) {
    int i = blockIdx.x * blockDim.x + threadIdx.x;
    if (i < n) {
        int v = g_off[i] + g_blk[i >> 10];
        g_off[i] = v;
        g_cnt[i] = v;
    }
    if (i == 0) g_off[n] = E;
}

// ---------------------------------------------------------------------------
// fill: int4-vectorized, 4 independent atomic position-claims per thread
// ---------------------------------------------------------------------------
__global__ void k_fill(const int* __restrict__ src, const int* __restrict__ dst, int E) {
    int gid = blockIdx.x * blockDim.x + threadIdx.x;
    int E4 = E >> 2;
    if (gid < E4) {
        int4 d4 = __ldg((const int4*)dst + gid);
        int4 s4 = __ldg((const int4*)src + gid);
        int p0 = atomicAdd(&g_cnt[d4.x], 1);
        int p1 = atomicAdd(&g_cnt[d4.y], 1);
        int p2 = atomicAdd(&g_cnt[d4.z], 1);
        int p3 = atomicAdd(&g_cnt[d4.w], 1);
        g_csr[p0] = s4.x;
        g_csr[p1] = s4.y;
        g_csr[p2] = s4.z;
        g_csr[p3] = s4.w;
    }
    if (gid == 0) {
        for (int e = E4 * 4; e < E; e++) {
            int pos = atomicAdd(&g_cnt[dst[e]], 1);
            g_csr[pos] = src[e];
        }
    }
}

// ---------------------------------------------------------------------------
// Gather + bf16 split (proven): warp per node, lane owns 16B, unroll-4.
// ---------------------------------------------------------------------------
__global__ void k_gather(const float* __restrict__ h, int N) {
    int node = blockIdx.x * 8 + (threadIdx.x >> 5);
    if (node >= N) return;
    int lane = threadIdx.x & 31;

    int beg = g_off[node];
    int end = g_off[node + 1];

    float4 a0 = make_float4(0.f, 0.f, 0.f, 0.f);
    float4 a1 = make_float4(0.f, 0.f, 0.f, 0.f);
    float4 a2 = make_float4(0.f, 0.f, 0.f, 0.f);
    float4 a3 = make_float4(0.f, 0.f, 0.f, 0.f);

    int e = beg;
    for (; e + 3 < end; e += 4) {
        int s0 = __ldg(&g_csr[e]);
        int s1 = __ldg(&g_csr[e + 1]);
        int s2 = __ldg(&g_csr[e + 2]);
        int s3 = __ldg(&g_csr[e + 3]);
        float4 v0 = __ldg((const float4*)(h + (size_t)s0 * D + lane * 4));
        float4 v1 = __ldg((const float4*)(h + (size_t)s1 * D + lane * 4));
        float4 v2 = __ldg((const float4*)(h + (size_t)s2 * D + lane * 4));
        float4 v3 = __ldg((const float4*)(h + (size_t)s3 * D + lane * 4));
        a0.x += v0.x; a0.y += v0.y; a0.z += v0.z; a0.w += v0.w;
        a1.x += v1.x; a1.y += v1.y; a1.z += v1.z; a1.w += v1.w;
        a2.x += v2.x; a2.y += v2.y; a2.z += v2.z; a2.w += v2.w;
        a3.x += v3.x; a3.y += v3.y; a3.z += v3.z; a3.w += v3.w;
    }
    for (; e < end; e++) {
        int s0 = __ldg(&g_csr[e]);
        float4 v0 = __ldg((const float4*)(h + (size_t)s0 * D + lane * 4));
        a0.x += v0.x; a0.y += v0.y; a0.z += v0.z; a0.w += v0.w;
    }
    float4 s4;
    s4.x = (a0.x + a1.x) + (a2.x + a3.x);
    s4.y = (a0.y + a1.y) + (a2.y + a3.y);
    s4.z = (a0.z + a1.z) + (a2.z + a3.z);
    s4.w = (a0.w + a1.w) + (a2.w + a3.w);

    __nv_bfloat16 h0 = __float2bfloat16(s4.x);
    __nv_bfloat16 h1 = __float2bfloat16(s4.y);
    __nv_bfloat16 h2 = __float2bfloat16(s4.z);
    __nv_bfloat16 h3 = __float2bfloat16(s4.w);
    __nv_bfloat16 l0 = __float2bfloat16(s4.x - __bfloat162float(h0));
    __nv_bfloat16 l1 = __float2bfloat16(s4.y - __bfloat162float(h1));
    __nv_bfloat16 l2 = __float2bfloat16(s4.z - __bfloat162float(h2));
    __nv_bfloat16 l3 = __float2bfloat16(s4.w - __bfloat162float(h3));

    unsigned idx = (unsigned)node * ROW_U32 + lane * 2;
    *(uint2*)&g_Ahi[idx] = make_uint2(pack_bf16x2(h0, h1), pack_bf16x2(h2, h3));
    *(uint2*)&g_Alo[idx] = make_uint2(pack_bf16x2(l0, l1), pack_bf16x2(l2, l3));
}

// ---------------------------------------------------------------------------
// Tensor-core GEMM (exact R9 version, proven in 170.2 config):
// 64-row tile, 2 CTAs/SM, scalar-LDS fragment loads.
// ---------------------------------------------------------------------------
#define SM_WHI 0
#define SM_WLO (SM_WHI + 128 * PADK * 2)      // 34816
#define SM_AHI (SM_WLO + 128 * PADK * 2)      // 69632
#define SM_ALO (SM_AHI + TM * PADK * 2)       // 87040
#define SM_BIAS (SM_ALO + TM * PADK * 2)      // 104448
#define SM_TOTAL (SM_BIAS + 512)              // 104960

__device__ __forceinline__ void mma_bf16(float& c0, float& c1, float& c2, float& c3,
                                         unsigned a0, unsigned a1, unsigned a2, unsigned a3,
                                         unsigned b0, unsigned b1) {
    asm volatile(
        "mma.sync.aligned.m16n8k16.row.col.f32.bf16.bf16.f32 "
        "{%0,%1,%2,%3}, {%4,%5,%6,%7}, {%8,%9}, {%0,%1,%2,%3};"
        : "+f"(c0), "+f"(c1), "+f"(c2), "+f"(c3)
        : "r"(a0), "r"(a1), "r"(a2), "r"(a3), "r"(b0), "r"(b1));
}

__global__ void __launch_bounds__(256, 2)
k_gemm_mma(const float* __restrict__ bias,
           float* __restrict__ out, int M) {
    extern __shared__ char sm[];
    int tid = threadIdx.x;
    int wid = tid >> 5;
    int lane = tid & 31;
    int m0 = blockIdx.x * TM;

    if (tid < 128) *(float*)(sm + SM_BIAS + tid * 4) = bias[tid];

    // W images -> smem (coalesced uint4, L2-broadcast)
    {
        const uint4* shi = (const uint4*)g_Whi;
        const uint4* slo = (const uint4*)g_Wlo;
        uint4* dhi = (uint4*)(sm + SM_WHI);
        uint4* dlo = (uint4*)(sm + SM_WLO);
        for (int i = tid; i < W_IMG_U32 / 4; i += 256) {
            dhi[i] = shi[i];
            dlo[i] = slo[i];
        }
    }

    // A images -> smem: pure uint4 copy
    {
        const uint4* sa = (const uint4*)g_Ahi + (size_t)m0 * (ROW_U32 / 4);
        const uint4* sl = (const uint4*)g_Alo + (size_t)m0 * (ROW_U32 / 4);
        uint4* da = (uint4*)(sm + SM_AHI);
        uint4* dl = (uint4*)(sm + SM_ALO);
#pragma unroll
        for (int j = 0; j < 5; j++) {
            int i = j * 256 + tid;
            if (i < TM * (ROW_U32 / 4)) {
                da[i] = sa[i];
                dl[i] = sl[i];
            }
        }
    }
    __syncthreads();

    int wm = (wid & 3) * 16;
    int wn = (wid >> 2) * 64;
    int g = lane >> 2;
    int t = lane & 3;

    float acc[8][4];
#pragma unroll
    for (int nt = 0; nt < 8; nt++)
#pragma unroll
        for (int i = 0; i < 4; i++) acc[nt][i] = 0.f;

#pragma unroll 1
    for (int p = 0; p < 3; p++) {
        const char* As = sm + ((p == 2) ? SM_ALO : SM_AHI);
        const char* Ws = sm + ((p == 1) ? SM_WLO : SM_WHI);
#pragma unroll 1
        for (int ks = 0; ks < 8; ks++) {
            int k0 = ks * 16;
            unsigned a[4];
            {
                unsigned base = (unsigned)((wm + g) * PADK + k0 + 2 * t) * 2;
                a[0] = *(const unsigned*)(As + base);
                a[1] = *(const unsigned*)(As + base + 8 * PADK * 2);
                a[2] = *(const unsigned*)(As + base + 16);
                a[3] = *(const unsigned*)(As + base + 8 * PADK * 2 + 16);
            }
            unsigned bb[8][2];
#pragma unroll
            for (int nt = 0; nt < 8; nt++) {
                unsigned base = (unsigned)((wn + nt * 8 + g) * PADK + k0 + 2 * t) * 2;
                bb[nt][0] = *(const unsigned*)(Ws + base);
                bb[nt][1] = *(const unsigned*)(Ws + base + 16);
            }
#pragma unroll
            for (int nt = 0; nt < 8; nt++)
                mma_bf16(acc[nt][0], acc[nt][1], acc[nt][2], acc[nt][3],
                         a[0], a[1], a[2], a[3], bb[nt][0], bb[nt][1]);
        }
    }

    // epilogue: bias + relu + float2 stores
    {
        const float* bs = (const float*)(sm + SM_BIAS);
        int r0 = wm + g;
        int gm0 = m0 + r0;
        int gm1 = gm0 + 8;
#pragma unroll
        for (int nt = 0; nt < 8; nt++) {
            int c = wn + nt * 8 + 2 * t;
            float2 bv = *(const float2*)(bs + c);
            if (gm0 < M) {
                float2 o;
                o.x = fmaxf(acc[nt][0] + bv.x, 0.f);
                o.y = fmaxf(acc[nt][1] + bv.y, 0.f);
                *(float2*)(out + (size_t)gm0 * D + c) = o;
            }
            if (gm1 < M) {
                float2 o;
                o.x = fmaxf(acc[nt][2] + bv.x, 0.f);
                o.y = fmaxf(acc[nt][3] + bv.y, 0.f);
                *(float2*)(out + (size_t)gm1 * D + c) = o;
            }
        }
    }
}

// ---------------------------------------------------------------------------
// Launch
// ---------------------------------------------------------------------------
extern "C" void kernel_launch(void* const* d_in, const int* in_sizes, int n_in,
                              void* d_out, int out_size) {
    const float* h    = (const float*)d_in[0];
    const int*   esrc = (const int*)d_in[1];
    const int*   edst = (const int*)d_in[2];
    const float* W    = (const float*)d_in[3];
    const float* b    = (const float*)d_in[4];
    float* out = (float*)d_out;

    int M = in_sizes[0] / D;   // 100000
    int E = in_sizes[1];       // 1600000

    cudaFuncSetAttribute(k_gemm_mma, cudaFuncAttributeMaxDynamicSharedMemorySize,
                         SM_TOTAL);

    int nb = (M + 1023) / 1024;
    int e4blocks = ((E >> 2) + 255) / 256;

    k_init<<<32 + (M + 255) / 256, 256>>>(W, M);
    k_hist<<<e4blocks, 256>>>(edst, E);
    k_scan1<<<nb, 256>>>(M);
    k_scan2<<<1, 256>>>(nb);
    k_scan3<<<(M + 255) / 256, 256>>>(M, E);
    k_fill<<<e4blocks, 256>>>(esrc, edst, E);
    k_gather<<<(M + 7) / 8, 256>>>(h, M);
    k_gemm_mma<<<(M + TM - 1) / TM, 256, SM_TOTAL>>>(b, out, M);
}

// round 14
// speedup vs baseline: 1.0243x; 1.0243x over previous
#include <cuda_runtime.h>
#include <cuda_bf16.h>
#include <cstdint>

#define D 128
#define MAXN 100000
#define MAXN_AL 100032               // padded to TM multiple
#define MAXE 1600000
#define PADK 136                     // padded bf16 row stride
#define ROW_U32 (PADK / 2)           // 68 u32 per bf16 row
#define W_IMG_U32 (128 * PADK / 2)   // 8704 u32 per W image
#define TM 64                        // GEMM CTA row tile

// ---------------- scratch (static device mem) ------------------------------
__device__ unsigned g_Whi[W_IMG_U32];
__device__ unsigned g_Wlo[W_IMG_U32];
__device__ unsigned g_Ahi[MAXN_AL * ROW_U32];   // zero-init (.bss)
__device__ unsigned g_Alo[MAXN_AL * ROW_U32];
__device__ int g_cnt[MAXN];
__device__ int g_off[MAXN + 1];
__device__ int g_csr[MAXE];
__device__ int g_blk[256];

__device__ __forceinline__ unsigned pack_bf16x2(__nv_bfloat16 a, __nv_bfloat16 b) {
    return ((unsigned)*(unsigned short*)&a) | ((unsigned)*(unsigned short*)&b << 16);
}

// ---------------------------------------------------------------------------
// init: W -> bf16 hi/lo images (blocks 0..31) + zero g_cnt (blocks 32..)
// ---------------------------------------------------------------------------
__global__ void k_init(const float* __restrict__ W, int n) {
    int b = blockIdx.x, t = threadIdx.x;
    if (b < 32) {
        int row = b * 4 + (t >> 6);
        int k = (t & 63) * 2;
        float f0 = W[row * D + k], f1 = W[row * D + k + 1];
        __nv_bfloat16 h0 = __float2bfloat16(f0);
        __nv_bfloat16 h1 = __float2bfloat16(f1);
        __nv_bfloat16 l0 = __float2bfloat16(f0 - __bfloat162float(h0));
        __nv_bfloat16 l1 = __float2bfloat16(f1 - __bfloat162float(h1));
        unsigned idx = (unsigned)(row * PADK + k) / 2;
        g_Whi[idx] = pack_bf16x2(h0, h1);
        g_Wlo[idx] = pack_bf16x2(l0, l1);
    } else {
        int i = (b - 32) * 256 + t;
        if (i < n) g_cnt[i] = 0;
    }
}

// ---------------------------------------------------------------------------
// histogram (proven R9 scalar grid-stride)
// ---------------------------------------------------------------------------
__global__ void k_hist(const int* __restrict__ dst, int E) {
    int i = blockIdx.x * blockDim.x + threadIdx.x;
    int stride = gridDim.x * blockDim.x;
    for (; i < E; i += stride) atomicAdd(&g_cnt[dst[i]], 1);
}

// ---------------------------------------------------------------------------
// 3-phase exclusive scan (verified)
// ---------------------------------------------------------------------------
__global__ void k_scan1(int n) {
    __shared__ int wsum[8];
    int b = blockIdx.x, t = threadIdx.x;
    int base = b * 1024 + t * 4;
    int v0 = (base + 0 < n) ? g_cnt[base + 0] : 0;
    int v1 = (base + 1 < n) ? g_cnt[base + 1] : 0;
    int v2 = (base + 2 < n) ? g_cnt[base + 2] : 0;
    int v3 = (base + 3 < n) ? g_cnt[base + 3] : 0;
    int s = v0 + v1 + v2 + v3;

    int lane = t & 31, w = t >> 5;
    int inc = s;
#pragma unroll
    for (int o = 1; o < 32; o <<= 1) {
        int x = __shfl_up_sync(0xffffffffu, inc, o);
        if (lane >= o) inc += x;
    }
    if (lane == 31) wsum[w] = inc;
    __syncthreads();
    if (t == 0) {
        int run = 0;
#pragma unroll
        for (int i = 0; i < 8; i++) { int tmp = wsum[i]; wsum[i] = run; run += tmp; }
        g_blk[b] = run;
    }
    __syncthreads();
    int excl = wsum[w] + inc - s;
    if (base + 0 < n) g_off[base + 0] = excl;
    if (base + 1 < n) g_off[base + 1] = excl + v0;
    if (base + 2 < n) g_off[base + 2] = excl + v0 + v1;
    if (base + 3 < n) g_off[base + 3] = excl + v0 + v1 + v2;
}

__global__ void k_scan2(int nb) {
    __shared__ int s[256];
    int t = threadIdx.x;
    s[t] = (t < nb) ? g_blk[t] : 0;
    __syncthreads();
    if (t == 0) {
        int run = 0;
        for (int i = 0; i < nb; i++) { int tmp = s[i]; s[i] = run; run += tmp; }
    }
    __syncthreads();
    if (t < nb) g_blk[t] = s[t];
}

__global__ void k_scan3(int n, int E) {
    int i = blockIdx.x * blockDim.x + threadIdx.x;
    if (i < n) {
        int v = g_off[i] + g_blk[i >> 10];
        g_off[i] = v;
        g_cnt[i] = v;
    }
    if (i == 0) g_off[n] = E;
}

// ---------------------------------------------------------------------------
// fill (proven R9 scalar grid-stride)
// ---------------------------------------------------------------------------
__global__ void k_fill(const int* __restrict__ src, const int* __restrict__ dst, int E) {
    int i = blockIdx.x * blockDim.x + threadIdx.x;
    int stride = gridDim.x * blockDim.x;
    for (; i < E; i += stride) {
        int pos = atomicAdd(&g_cnt[dst[i]], 1);
        g_csr[pos] = src[i];
    }
}

// ---------------------------------------------------------------------------
// Gather + bf16 split (proven): warp per node, lane owns 16B, unroll-4.
// ---------------------------------------------------------------------------
__global__ void k_gather(const float* __restrict__ h, int N) {
    int node = blockIdx.x * 8 + (threadIdx.x >> 5);
    if (node >= N) return;
    int lane = threadIdx.x & 31;

    int beg = g_off[node];
    int end = g_off[node + 1];

    float4 a0 = make_float4(0.f, 0.f, 0.f, 0.f);
    float4 a1 = make_float4(0.f, 0.f, 0.f, 0.f);
    float4 a2 = make_float4(0.f, 0.f, 0.f, 0.f);
    float4 a3 = make_float4(0.f, 0.f, 0.f, 0.f);

    int e = beg;
    for (; e + 3 < end; e += 4) {
        int s0 = __ldg(&g_csr[e]);
        int s1 = __ldg(&g_csr[e + 1]);
        int s2 = __ldg(&g_csr[e + 2]);
        int s3 = __ldg(&g_csr[e + 3]);
        float4 v0 = __ldg((const float4*)(h + (size_t)s0 * D + lane * 4));
        float4 v1 = __ldg((const float4*)(h + (size_t)s1 * D + lane * 4));
        float4 v2 = __ldg((const float4*)(h + (size_t)s2 * D + lane * 4));
        float4 v3 = __ldg((const float4*)(h + (size_t)s3 * D + lane * 4));
        a0.x += v0.x; a0.y += v0.y; a0.z += v0.z; a0.w += v0.w;
        a1.x += v1.x; a1.y += v1.y; a1.z += v1.z; a1.w += v1.w;
        a2.x += v2.x; a2.y += v2.y; a2.z += v2.z; a2.w += v2.w;
        a3.x += v3.x; a3.y += v3.y; a3.z += v3.z; a3.w += v3.w;
    }
    for (; e < end; e++) {
        int s0 = __ldg(&g_csr[e]);
        float4 v0 = __ldg((const float4*)(h + (size_t)s0 * D + lane * 4));
        a0.x += v0.x; a0.y += v0.y; a0.z += v0.z; a0.w += v0.w;
    }
    float4 s4;
    s4.x = (a0.x + a1.x) + (a2.x + a3.x);
    s4.y = (a0.y + a1.y) + (a2.y + a3.y);
    s4.z = (a0.z + a1.z) + (a2.z + a3.z);
    s4.w = (a0.w + a1.w) + (a2.w + a3.w);

    __nv_bfloat16 h0 = __float2bfloat16(s4.x);
    __nv_bfloat16 h1 = __float2bfloat16(s4.y);
    __nv_bfloat16 h2 = __float2bfloat16(s4.z);
    __nv_bfloat16 h3 = __float2bfloat16(s4.w);
    __nv_bfloat16 l0 = __float2bfloat16(s4.x - __bfloat162float(h0));
    __nv_bfloat16 l1 = __float2bfloat16(s4.y - __bfloat162float(h1));
    __nv_bfloat16 l2 = __float2bfloat16(s4.z - __bfloat162float(h2));
    __nv_bfloat16 l3 = __float2bfloat16(s4.w - __bfloat162float(h3));

    unsigned idx = (unsigned)node * ROW_U32 + lane * 2;
    *(uint2*)&g_Ahi[idx] = make_uint2(pack_bf16x2(h0, h1), pack_bf16x2(h2, h3));
    *(uint2*)&g_Alo[idx] = make_uint2(pack_bf16x2(l0, l1), pack_bf16x2(l2, l3));
}

// ---------------------------------------------------------------------------
// Tensor-core GEMM: 64-row tile, 2 CTAs/SM, LDSM fragment loads
// (R12 GEMM — verified correct, -4.9us vs scalar-LDS by R12/R13 subtraction)
// ---------------------------------------------------------------------------
#define SM_WHI 0
#define SM_WLO (SM_WHI + 128 * PADK * 2)      // 34816
#define SM_AHI (SM_WLO + 128 * PADK * 2)      // 69632
#define SM_ALO (SM_AHI + TM * PADK * 2)       // 87040
#define SM_BIAS (SM_ALO + TM * PADK * 2)      // 104448
#define SM_TOTAL (SM_BIAS + 512)              // 104960

__device__ __forceinline__ void mma_bf16(float& c0, float& c1, float& c2, float& c3,
                                         unsigned a0, unsigned a1, unsigned a2, unsigned a3,
                                         unsigned b0, unsigned b1) {
    asm volatile(
        "mma.sync.aligned.m16n8k16.row.col.f32.bf16.bf16.f32 "
        "{%0,%1,%2,%3}, {%4,%5,%6,%7}, {%8,%9}, {%0,%1,%2,%3};"
        : "+f"(c0), "+f"(c1), "+f"(c2), "+f"(c3)
        : "r"(a0), "r"(a1), "r"(a2), "r"(a3), "r"(b0), "r"(b1));
}

__device__ __forceinline__ void ldsm_x4(unsigned& r0, unsigned& r1,
                                        unsigned& r2, unsigned& r3, unsigned addr) {
    asm volatile("ldmatrix.sync.aligned.m8n8.x4.shared.b16 {%0,%1,%2,%3}, [%4];"
                 : "=r"(r0), "=r"(r1), "=r"(r2), "=r"(r3) : "r"(addr));
}

__global__ void __launch_bounds__(256, 2)
k_gemm_mma(const float* __restrict__ bias,
           float* __restrict__ out, int M) {
    extern __shared__ char sm[];
    int tid = threadIdx.x;
    int wid = tid >> 5;
    int lane = tid & 31;
    int m0 = blockIdx.x * TM;

    if (tid < 128) *(float*)(sm + SM_BIAS + tid * 4) = bias[tid];

    // W images -> smem (coalesced uint4, L2-broadcast)
    {
        const uint4* shi = (const uint4*)g_Whi;
        const uint4* slo = (const uint4*)g_Wlo;
        uint4* dhi = (uint4*)(sm + SM_WHI);
        uint4* dlo = (uint4*)(sm + SM_WLO);
        for (int i = tid; i < W_IMG_U32 / 4; i += 256) {
            dhi[i] = shi[i];
            dlo[i] = slo[i];
        }
    }

    // A images -> smem: pure uint4 copy
    {
        const uint4* sa = (const uint4*)g_Ahi + (size_t)m0 * (ROW_U32 / 4);
        const uint4* sl = (const uint4*)g_Alo + (size_t)m0 * (ROW_U32 / 4);
        uint4* da = (uint4*)(sm + SM_AHI);
        uint4* dl = (uint4*)(sm + SM_ALO);
#pragma unroll
        for (int j = 0; j < 5; j++) {
            int i = j * 256 + tid;
            if (i < TM * (ROW_U32 / 4)) {
                da[i] = sa[i];
                dl[i] = sl[i];
            }
        }
    }
    __syncthreads();

    int wm = (wid & 3) * 16;
    int wn = (wid >> 2) * 64;

    // LDSM per-lane offsets (bytes). q = lane>>3 (matrix id), r = lane&7.
    int q = lane >> 3, r = lane & 7;
    unsigned a_off = (unsigned)((wm + ((q & 1) << 3) + r) * PADK + ((q >> 1) << 3)) * 2;
    unsigned b_off[4];
#pragma unroll
    for (int j = 0; j < 4; j++)
        b_off[j] = (unsigned)((wn + j * 16 + ((lane >> 4) << 3) + r) * PADK
                              + (((lane >> 3) & 1) << 3)) * 2;

    unsigned sm_u32 = (unsigned)__cvta_generic_to_shared(sm);

    float acc[8][4];
#pragma unroll
    for (int nt = 0; nt < 8; nt++)
#pragma unroll
        for (int i = 0; i < 4; i++) acc[nt][i] = 0.f;

#pragma unroll 1
    for (int p = 0; p < 3; p++) {
        unsigned As = sm_u32 + ((p == 2) ? SM_ALO : SM_AHI);
        unsigned Ws = sm_u32 + ((p == 1) ? SM_WLO : SM_WHI);
#pragma unroll 1
        for (int ks = 0; ks < 8; ks++) {
            unsigned koff = (unsigned)(ks * 16) * 2;
            unsigned a[4];
            ldsm_x4(a[0], a[1], a[2], a[3], As + a_off + koff);
            unsigned bb[8][2];
#pragma unroll
            for (int j = 0; j < 4; j++)
                ldsm_x4(bb[2 * j][0], bb[2 * j][1], bb[2 * j + 1][0], bb[2 * j + 1][1],
                        Ws + b_off[j] + koff);
#pragma unroll
            for (int nt = 0; nt < 8; nt++)
                mma_bf16(acc[nt][0], acc[nt][1], acc[nt][2], acc[nt][3],
                         a[0], a[1], a[2], a[3], bb[nt][0], bb[nt][1]);
        }
    }

    // epilogue: bias + relu + float2 stores
    {
        const float* bs = (const float*)(sm + SM_BIAS);
        int g2 = lane >> 2;
        int t2 = lane & 3;
        int r0 = wm + g2;
        int gm0 = m0 + r0;
        int gm1 = gm0 + 8;
#pragma unroll
        for (int nt = 0; nt < 8; nt++) {
            int c = wn + nt * 8 + 2 * t2;
            float2 bv = *(const float2*)(bs + c);
            if (gm0 < M) {
                float2 o;
                o.x = fmaxf(acc[nt][0] + bv.x, 0.f);
                o.y = fmaxf(acc[nt][1] + bv.y, 0.f);
                *(float2*)(out + (size_t)gm0 * D + c) = o;
            }
            if (gm1 < M) {
                float2 o;
                o.x = fmaxf(acc[nt][2] + bv.x, 0.f);
                o.y = fmaxf(acc[nt][3] + bv.y, 0.f);
                *(float2*)(out + (size_t)gm1 * D + c) = o;
            }
        }
    }
}

// ---------------------------------------------------------------------------
// Launch
// ---------------------------------------------------------------------------
extern "C" void kernel_launch(void* const* d_in, const int* in_sizes, int n_in,
                              void* d_out, int out_size) {
    const float* h    = (const float*)d_in[0];
    const int*   esrc = (const int*)d_in[1];
    const int*   edst = (const int*)d_in[2];
    const float* W    = (const float*)d_in[3];
    const float* b    = (const float*)d_in[4];
    float* out = (float*)d_out;

    int M = in_sizes[0] / D;   // 100000
    int E = in_sizes[1];       // 1600000

    cudaFuncSetAttribute(k_gemm_mma, cudaFuncAttributeMaxDynamicSharedMemorySize,
                         SM_TOTAL);

    int nb = (M + 1023) / 1024;

    k_init<<<32 + (M + 255) / 256, 256>>>(W, M);
    k_hist<<<1024, 256>>>(edst, E);
    k_scan1<<<nb, 256>>>(M);
    k_scan2<<<1, 256>>>(nb);
    k_scan3<<<(M + 255) / 256, 256>>>(M, E);
    k_fill<<<1024, 256>>>(esrc, edst, E);
    k_gather<<<(M + 7) / 8, 256>>>(h, M);
    k_gemm_mma<<<(M + TM - 1) / TM, 256, SM_TOTAL>>>(b, out, M);
}

// round 15
// speedup vs baseline: 1.0864x; 1.0606x over previous
#include <cuda_runtime.h>
#include <cuda_bf16.h>
#include <cuda_fp16.h>
#include <cstdint>

#define D 128
#define MAXN 100000
#define MAXN_AL 100032               // padded to TM multiple
#define MAXE 1600000
#define PADK 136                     // padded bf16 row stride
#define ROW_U32 (PADK / 2)           // 68 u32 per bf16 row
#define W_IMG_U32 (128 * PADK / 2)   // 8704 u32 per W image
#define TM 64                        // GEMM CTA row tile

// ---------------- scratch (static device mem) ------------------------------
__device__ unsigned g_Whi[W_IMG_U32];
__device__ unsigned g_Wlo[W_IMG_U32];
__device__ unsigned g_h16[MAXN * 64];           // h as fp16, [node][128] (25.6MB)
__device__ unsigned g_Ahi[MAXN_AL * ROW_U32];   // zero-init (.bss)
__device__ unsigned g_Alo[MAXN_AL * ROW_U32];
__device__ int g_cnt[MAXN];
__device__ int g_off[MAXN + 1];
__device__ int g_csr[MAXE];
__device__ int g_blk[256];

__device__ __forceinline__ unsigned pack_bf16x2(__nv_bfloat16 a, __nv_bfloat16 b) {
    return ((unsigned)*(unsigned short*)&a) | ((unsigned)*(unsigned short*)&b << 16);
}

// ---------------------------------------------------------------------------
// init (fused): W -> bf16 hi/lo images | zero g_cnt | h -> fp16 image
// ---------------------------------------------------------------------------
__global__ void k_init(const float* __restrict__ W, const float* __restrict__ h,
                       int n, int zeroBlocks) {
    int b = blockIdx.x, t = threadIdx.x;
    if (b < 32) {                            // W prep
        int row = b * 4 + (t >> 6);
        int k = (t & 63) * 2;
        float f0 = W[row * D + k], f1 = W[row * D + k + 1];
        __nv_bfloat16 h0 = __float2bfloat16(f0);
        __nv_bfloat16 h1 = __float2bfloat16(f1);
        __nv_bfloat16 l0 = __float2bfloat16(f0 - __bfloat162float(h0));
        __nv_bfloat16 l1 = __float2bfloat16(f1 - __bfloat162float(h1));
        unsigned idx = (unsigned)(row * PADK + k) / 2;
        g_Whi[idx] = pack_bf16x2(h0, h1);
        g_Wlo[idx] = pack_bf16x2(l0, l1);
    } else if (b < 32 + zeroBlocks) {        // zero g_cnt
        int i = (b - 32) * 256 + t;
        if (i < n) g_cnt[i] = 0;
    } else {                                 // h -> fp16 (one float4 per thread)
        int i = (b - 32 - zeroBlocks) * 256 + t;      // float4 index
        int n4 = n * 32;                              // n*128/4
        if (i < n4) {
            float4 v = __ldg((const float4*)h + i);
            half2 p0 = __float22half2_rn(make_float2(v.x, v.y));
            half2 p1 = __float22half2_rn(make_float2(v.z, v.w));
            uint2 o;
            o.x = *(unsigned*)&p0;
            o.y = *(unsigned*)&p1;
            *((uint2*)g_h16 + i) = o;
        }
    }
}

// ---------------------------------------------------------------------------
// histogram (proven R9 scalar grid-stride)
// ---------------------------------------------------------------------------
__global__ void k_hist(const int* __restrict__ dst, int E) {
    int i = blockIdx.x * blockDim.x + threadIdx.x;
    int stride = gridDim.x * blockDim.x;
    for (; i < E; i += stride) atomicAdd(&g_cnt[dst[i]], 1);
}

// ---------------------------------------------------------------------------
// 3-phase exclusive scan (verified)
// ---------------------------------------------------------------------------
__global__ void k_scan1(int n) {
    __shared__ int wsum[8];
    int b = blockIdx.x, t = threadIdx.x;
    int base = b * 1024 + t * 4;
    int v0 = (base + 0 < n) ? g_cnt[base + 0] : 0;
    int v1 = (base + 1 < n) ? g_cnt[base + 1] : 0;
    int v2 = (base + 2 < n) ? g_cnt[base + 2] : 0;
    int v3 = (base + 3 < n) ? g_cnt[base + 3] : 0;
    int s = v0 + v1 + v2 + v3;

    int lane = t & 31, w = t >> 5;
    int inc = s;
#pragma unroll
    for (int o = 1; o < 32; o <<= 1) {
        int x = __shfl_up_sync(0xffffffffu, inc, o);
        if (lane >= o) inc += x;
    }
    if (lane == 31) wsum[w] = inc;
    __syncthreads();
    if (t == 0) {
        int run = 0;
#pragma unroll
        for (int i = 0; i < 8; i++) { int tmp = wsum[i]; wsum[i] = run; run += tmp; }
        g_blk[b] = run;
    }
    __syncthreads();
    int excl = wsum[w] + inc - s;
    if (base + 0 < n) g_off[base + 0] = excl;
    if (base + 1 < n) g_off[base + 1] = excl + v0;
    if (base + 2 < n) g_off[base + 2] = excl + v0 + v1;
    if (base + 3 < n) g_off[base + 3] = excl + v0 + v1 + v2;
}

__global__ void k_scan2(int nb) {
    __shared__ int s[256];
    int t = threadIdx.x;
    s[t] = (t < nb) ? g_blk[t] : 0;
    __syncthreads();
    if (t == 0) {
        int run = 0;
        for (int i = 0; i < nb; i++) { int tmp = s[i]; s[i] = run; run += tmp; }
    }
    __syncthreads();
    if (t < nb) g_blk[t] = s[t];
}

__global__ void k_scan3(int n, int E) {
    int i = blockIdx.x * blockDim.x + threadIdx.x;
    if (i < n) {
        int v = g_off[i] + g_blk[i >> 10];
        g_off[i] = v;
        g_cnt[i] = v;
    }
    if (i == 0) g_off[n] = E;
}

// ---------------------------------------------------------------------------
// fill (proven R9 scalar grid-stride)
// ---------------------------------------------------------------------------
__global__ void k_fill(const int* __restrict__ src, const int* __restrict__ dst, int E) {
    int i = blockIdx.x * blockDim.x + threadIdx.x;
    int stride = gridDim.x * blockDim.x;
    for (; i < E; i += stride) {
        int pos = atomicAdd(&g_cnt[dst[i]], 1);
        g_csr[pos] = src[i];
    }
}

// ---------------------------------------------------------------------------
// Gather from fp16 image + bf16 split: warp per node, lane owns 4 halves (8B),
// unroll-4. fp32 accumulation; output split identical to R9.
// ---------------------------------------------------------------------------
__global__ void k_gather(int N) {
    int node = blockIdx.x * 8 + (threadIdx.x >> 5);
    if (node >= N) return;
    int lane = threadIdx.x & 31;

    int beg = g_off[node];
    int end = g_off[node + 1];

    const uint2* hp = (const uint2*)g_h16;   // 32 uint2 per node row

    float4 a0 = make_float4(0.f, 0.f, 0.f, 0.f);
    float4 a1 = make_float4(0.f, 0.f, 0.f, 0.f);
    float4 a2 = make_float4(0.f, 0.f, 0.f, 0.f);
    float4 a3 = make_float4(0.f, 0.f, 0.f, 0.f);

    int e = beg;
    for (; e + 3 < end; e += 4) {
        int s0 = __ldg(&g_csr[e]);
        int s1 = __ldg(&g_csr[e + 1]);
        int s2 = __ldg(&g_csr[e + 2]);
        int s3 = __ldg(&g_csr[e + 3]);
        uint2 v0 = __ldg(&hp[(size_t)s0 * 32 + lane]);
        uint2 v1 = __ldg(&hp[(size_t)s1 * 32 + lane]);
        uint2 v2 = __ldg(&hp[(size_t)s2 * 32 + lane]);
        uint2 v3 = __ldg(&hp[(size_t)s3 * 32 + lane]);
        float2 f;
        f = __half22float2(*(half2*)&v0.x); a0.x += f.x; a0.y += f.y;
        f = __half22float2(*(half2*)&v0.y); a0.z += f.x; a0.w += f.y;
        f = __half22float2(*(half2*)&v1.x); a1.x += f.x; a1.y += f.y;
        f = __half22float2(*(half2*)&v1.y); a1.z += f.x; a1.w += f.y;
        f = __half22float2(*(half2*)&v2.x); a2.x += f.x; a2.y += f.y;
        f = __half22float2(*(half2*)&v2.y); a2.z += f.x; a2.w += f.y;
        f = __half22float2(*(half2*)&v3.x); a3.x += f.x; a3.y += f.y;
        f = __half22float2(*(half2*)&v3.y); a3.z += f.x; a3.w += f.y;
    }
    for (; e < end; e++) {
        int s0 = __ldg(&g_csr[e]);
        uint2 v0 = __ldg(&hp[(size_t)s0 * 32 + lane]);
        float2 f;
        f = __half22float2(*(half2*)&v0.x); a0.x += f.x; a0.y += f.y;
        f = __half22float2(*(half2*)&v0.y); a0.z += f.x; a0.w += f.y;
    }
    float4 s4;
    s4.x = (a0.x + a1.x) + (a2.x + a3.x);
    s4.y = (a0.y + a1.y) + (a2.y + a3.y);
    s4.z = (a0.z + a1.z) + (a2.z + a3.z);
    s4.w = (a0.w + a1.w) + (a2.w + a3.w);

    __nv_bfloat16 h0 = __float2bfloat16(s4.x);
    __nv_bfloat16 h1 = __float2bfloat16(s4.y);
    __nv_bfloat16 h2 = __float2bfloat16(s4.z);
    __nv_bfloat16 h3 = __float2bfloat16(s4.w);
    __nv_bfloat16 l0 = __float2bfloat16(s4.x - __bfloat162float(h0));
    __nv_bfloat16 l1 = __float2bfloat16(s4.y - __bfloat162float(h1));
    __nv_bfloat16 l2 = __float2bfloat16(s4.z - __bfloat162float(h2));
    __nv_bfloat16 l3 = __float2bfloat16(s4.w - __bfloat162float(h3));

    unsigned idx = (unsigned)node * ROW_U32 + lane * 2;
    *(uint2*)&g_Ahi[idx] = make_uint2(pack_bf16x2(h0, h1), pack_bf16x2(h2, h3));
    *(uint2*)&g_Alo[idx] = make_uint2(pack_bf16x2(l0, l1), pack_bf16x2(l2, l3));
}

// ---------------------------------------------------------------------------
// Tensor-core GEMM (exact R9 version, proven in the 170.2 config):
// 64-row tile, 2 CTAs/SM, scalar-LDS fragment loads.
// ---------------------------------------------------------------------------
#define SM_WHI 0
#define SM_WLO (SM_WHI + 128 * PADK * 2)      // 34816
#define SM_AHI (SM_WLO + 128 * PADK * 2)      // 69632
#define SM_ALO (SM_AHI + TM * PADK * 2)       // 87040
#define SM_BIAS (SM_ALO + TM * PADK * 2)      // 104448
#define SM_TOTAL (SM_BIAS + 512)              // 104960

__device__ __forceinline__ void mma_bf16(float& c0, float& c1, float& c2, float& c3,
                                         unsigned a0, unsigned a1, unsigned a2, unsigned a3,
                                         unsigned b0, unsigned b1) {
    asm volatile(
        "mma.sync.aligned.m16n8k16.row.col.f32.bf16.bf16.f32 "
        "{%0,%1,%2,%3}, {%4,%5,%6,%7}, {%8,%9}, {%0,%1,%2,%3};"
        : "+f"(c0), "+f"(c1), "+f"(c2), "+f"(c3)
        : "r"(a0), "r"(a1), "r"(a2), "r"(a3), "r"(b0), "r"(b1));
}

__global__ void __launch_bounds__(256, 2)
k_gemm_mma(const float* __restrict__ bias,
           float* __restrict__ out, int M) {
    extern __shared__ char sm[];
    int tid = threadIdx.x;
    int wid = tid >> 5;
    int lane = tid & 31;
    int m0 = blockIdx.x * TM;

    if (tid < 128) *(float*)(sm + SM_BIAS + tid * 4) = bias[tid];

    // W images -> smem (coalesced uint4, L2-broadcast)
    {
        const uint4* shi = (const uint4*)g_Whi;
        const uint4* slo = (const uint4*)g_Wlo;
        uint4* dhi = (uint4*)(sm + SM_WHI);
        uint4* dlo = (uint4*)(sm + SM_WLO);
        for (int i = tid; i < W_IMG_U32 / 4; i += 256) {
            dhi[i] = shi[i];
            dlo[i] = slo[i];
        }
    }

    // A images -> smem: pure uint4 copy
    {
        const uint4* sa = (const uint4*)g_Ahi + (size_t)m0 * (ROW_U32 / 4);
        const uint4* sl = (const uint4*)g_Alo + (size_t)m0 * (ROW_U32 / 4);
        uint4* da = (uint4*)(sm + SM_AHI);
        uint4* dl = (uint4*)(sm + SM_ALO);
#pragma unroll
        for (int j = 0; j < 5; j++) {
            int i = j * 256 + tid;
            if (i < TM * (ROW_U32 / 4)) {
                da[i] = sa[i];
                dl[i] = sl[i];
            }
        }
    }
    __syncthreads();

    int wm = (wid & 3) * 16;
    int wn = (wid >> 2) * 64;
    int g = lane >> 2;
    int t = lane & 3;

    float acc[8][4];
#pragma unroll
    for (int nt = 0; nt < 8; nt++)
#pragma unroll
        for (int i = 0; i < 4; i++) acc[nt][i] = 0.f;

#pragma unroll 1
    for (int p = 0; p < 3; p++) {
        const char* As = sm + ((p == 2) ? SM_ALO : SM_AHI);
        const char* Ws = sm + ((p == 1) ? SM_WLO : SM_WHI);
#pragma unroll 1
        for (int ks = 0; ks < 8; ks++) {
            int k0 = ks * 16;
            unsigned a[4];
            {
                unsigned base = (unsigned)((wm + g) * PADK + k0 + 2 * t) * 2;
                a[0] = *(const unsigned*)(As + base);
                a[1] = *(const unsigned*)(As + base + 8 * PADK * 2);
                a[2] = *(const unsigned*)(As + base + 16);
                a[3] = *(const unsigned*)(As + base + 8 * PADK * 2 + 16);
            }
            unsigned bb[8][2];
#pragma unroll
            for (int nt = 0; nt < 8; nt++) {
                unsigned base = (unsigned)((wn + nt * 8 + g) * PADK + k0 + 2 * t) * 2;
                bb[nt][0] = *(const unsigned*)(Ws + base);
                bb[nt][1] = *(const unsigned*)(Ws + base + 16);
            }
#pragma unroll
            for (int nt = 0; nt < 8; nt++)
                mma_bf16(acc[nt][0], acc[nt][1], acc[nt][2], acc[nt][3],
                         a[0], a[1], a[2], a[3], bb[nt][0], bb[nt][1]);
        }
    }

    // epilogue: bias + relu + float2 stores
    {
        const float* bs = (const float*)(sm + SM_BIAS);
        int r0 = wm + g;
        int gm0 = m0 + r0;
        int gm1 = gm0 + 8;
#pragma unroll
        for (int nt = 0; nt < 8; nt++) {
            int c = wn + nt * 8 + 2 * t;
            float2 bv = *(const float2*)(bs + c);
            if (gm0 < M) {
                float2 o;
                o.x = fmaxf(acc[nt][0] + bv.x, 0.f);
                o.y = fmaxf(acc[nt][1] + bv.y, 0.f);
                *(float2*)(out + (size_t)gm0 * D + c) = o;
            }
            if (gm1 < M) {
                float2 o;
                o.x = fmaxf(acc[nt][2] + bv.x, 0.f);
                o.y = fmaxf(acc[nt][3] + bv.y, 0.f);
                *(float2*)(out + (size_t)gm1 * D + c) = o;
            }
        }
    }
}

// ---------------------------------------------------------------------------
// Launch
// ---------------------------------------------------------------------------
extern "C" void kernel_launch(void* const* d_in, const int* in_sizes, int n_in,
                              void* d_out, int out_size) {
    const float* h    = (const float*)d_in[0];
    const int*   esrc = (const int*)d_in[1];
    const int*   edst = (const int*)d_in[2];
    const float* W    = (const float*)d_in[3];
    const float* b    = (const float*)d_in[4];
    float* out = (float*)d_out;

    int M = in_sizes[0] / D;   // 100000
    int E = in_sizes[1];       // 1600000

    cudaFuncSetAttribute(k_gemm_mma, cudaFuncAttributeMaxDynamicSharedMemorySize,
                         SM_TOTAL);

    int nb = (M + 1023) / 1024;
    int zeroBlocks = (M + 255) / 256;          // 391
    int convBlocks = (M * 32 + 255) / 256;     // 12500

    k_init<<<32 + zeroBlocks + convBlocks, 256>>>(W, h, M, zeroBlocks);
    k_hist<<<1024, 256>>>(edst, E);
    k_scan1<<<nb, 256>>>(M);
    k_scan2<<<1, 256>>>(nb);
    k_scan3<<<(M + 255) / 256, 256>>>(M, E);
    k_fill<<<1024, 256>>>(esrc, edst, E);
    k_gather<<<(M + 7) / 8, 256>>>(M);
    k_gemm_mma<<<(M + TM - 1) / TM, 256, SM_TOTAL>>>(b, out, M);
}

// round 16
// speedup vs baseline: 1.2784x; 1.1768x over previous
#include <cuda_runtime.h>
#include <cuda_fp16.h>
#include <cstdint>

#define D 128
#define MAXN 100000
#define MAXN_AL 100032               // padded to TM multiple
#define MAXE 1600000
#define PADK 136                     // padded fp16 row stride
#define ROW_U32 (PADK / 2)           // 68 u32 per fp16 row
#define W_IMG_U32 (128 * PADK / 2)   // 8704 u32 for W image
#define TM 64                        // GEMM CTA row tile

// ---------------- scratch (static device mem) ------------------------------
__device__ unsigned g_W16[W_IMG_U32];           // W as fp16, [n][PADK]
__device__ unsigned g_h16[MAXN * 64];           // h as fp16, [node][128] (25.6MB)
__device__ unsigned g_A16[MAXN_AL * ROW_U32];   // gathered A as fp16 (zero-init)
__device__ int g_cnt[MAXN];
__device__ int g_off[MAXN + 1];
__device__ int g_csr[MAXE];
__device__ int g_blk[256];

// ---------------------------------------------------------------------------
// init (fused): W -> fp16 image | zero g_cnt | h -> fp16 image
// ---------------------------------------------------------------------------
__global__ void k_init(const float* __restrict__ W, const float* __restrict__ h,
                       int n, int zeroBlocks) {
    int b = blockIdx.x, t = threadIdx.x;
    if (b < 32) {                            // W prep
        int row = b * 4 + (t >> 6);
        int k = (t & 63) * 2;
        half2 p = __float22half2_rn(make_float2(W[row * D + k], W[row * D + k + 1]));
        g_W16[(unsigned)(row * PADK + k) / 2] = *(unsigned*)&p;
    } else if (b < 32 + zeroBlocks) {        // zero g_cnt
        int i = (b - 32) * 256 + t;
        if (i < n) g_cnt[i] = 0;
    } else {                                 // h -> fp16 (one float4 per thread)
        int i = (b - 32 - zeroBlocks) * 256 + t;
        int n4 = n * 32;
        if (i < n4) {
            float4 v = __ldg((const float4*)h + i);
            half2 p0 = __float22half2_rn(make_float2(v.x, v.y));
            half2 p1 = __float22half2_rn(make_float2(v.z, v.w));
            uint2 o;
            o.x = *(unsigned*)&p0;
            o.y = *(unsigned*)&p1;
            *((uint2*)g_h16 + i) = o;
        }
    }
}

// ---------------------------------------------------------------------------
// histogram (proven scalar grid-stride)
// ---------------------------------------------------------------------------
__global__ void k_hist(const int* __restrict__ dst, int E) {
    int i = blockIdx.x * blockDim.x + threadIdx.x;
    int stride = gridDim.x * blockDim.x;
    for (; i < E; i += stride) atomicAdd(&g_cnt[dst[i]], 1);
}

// ---------------------------------------------------------------------------
// 3-phase exclusive scan (verified)
// ---------------------------------------------------------------------------
__global__ void k_scan1(int n) {
    __shared__ int wsum[8];
    int b = blockIdx.x, t = threadIdx.x;
    int base = b * 1024 + t * 4;
    int v0 = (base + 0 < n) ? g_cnt[base + 0] : 0;
    int v1 = (base + 1 < n) ? g_cnt[base + 1] : 0;
    int v2 = (base + 2 < n) ? g_cnt[base + 2] : 0;
    int v3 = (base + 3 < n) ? g_cnt[base + 3] : 0;
    int s = v0 + v1 + v2 + v3;

    int lane = t & 31, w = t >> 5;
    int inc = s;
#pragma unroll
    for (int o = 1; o < 32; o <<= 1) {
        int x = __shfl_up_sync(0xffffffffu, inc, o);
        if (lane >= o) inc += x;
    }
    if (lane == 31) wsum[w] = inc;
    __syncthreads();
    if (t == 0) {
        int run = 0;
#pragma unroll
        for (int i = 0; i < 8; i++) { int tmp = wsum[i]; wsum[i] = run; run += tmp; }
        g_blk[b] = run;
    }
    __syncthreads();
    int excl = wsum[w] + inc - s;
    if (base + 0 < n) g_off[base + 0] = excl;
    if (base + 1 < n) g_off[base + 1] = excl + v0;
    if (base + 2 < n) g_off[base + 2] = excl + v0 + v1;
    if (base + 3 < n) g_off[base + 3] = excl + v0 + v1 + v2;
}

__global__ void k_scan2(int nb) {
    __shared__ int s[256];
    int t = threadIdx.x;
    s[t] = (t < nb) ? g_blk[t] : 0;
    __syncthreads();
    if (t == 0) {
        int run = 0;
        for (int i = 0; i < nb; i++) { int tmp = s[i]; s[i] = run; run += tmp; }
    }
    __syncthreads();
    if (t < nb) g_blk[t] = s[t];
}

__global__ void k_scan3(int n, int E) {
    int i = blockIdx.x * blockDim.x + threadIdx.x;
    if (i < n) {
        int v = g_off[i] + g_blk[i >> 10];
        g_off[i] = v;
        g_cnt[i] = v;
    }
    if (i == 0) g_off[n] = E;
}

// ---------------------------------------------------------------------------
// fill (proven scalar grid-stride)
// ---------------------------------------------------------------------------
__global__ void k_fill(const int* __restrict__ src, const int* __restrict__ dst, int E) {
    int i = blockIdx.x * blockDim.x + threadIdx.x;
    int stride = gridDim.x * blockDim.x;
    for (; i < E; i += stride) {
        int pos = atomicAdd(&g_cnt[dst[i]], 1);
        g_csr[pos] = src[i];
    }
}

// ---------------------------------------------------------------------------
// Gather from fp16 image -> fp16 A image (fp32 accumulation in regs).
// Warp per node, lane owns 4 halves (8B), unroll-4.
// ---------------------------------------------------------------------------
__global__ void k_gather(int N) {
    int node = blockIdx.x * 8 + (threadIdx.x >> 5);
    if (node >= N) return;
    int lane = threadIdx.x & 31;

    int beg = g_off[node];
    int end = g_off[node + 1];

    const uint2* hp = (const uint2*)g_h16;

    float4 a0 = make_float4(0.f, 0.f, 0.f, 0.f);
    float4 a1 = make_float4(0.f, 0.f, 0.f, 0.f);
    float4 a2 = make_float4(0.f, 0.f, 0.f, 0.f);
    float4 a3 = make_float4(0.f, 0.f, 0.f, 0.f);

    int e = beg;
    for (; e + 3 < end; e += 4) {
        int s0 = __ldg(&g_csr[e]);
        int s1 = __ldg(&g_csr[e + 1]);
        int s2 = __ldg(&g_csr[e + 2]);
        int s3 = __ldg(&g_csr[e + 3]);
        uint2 v0 = __ldg(&hp[(size_t)s0 * 32 + lane]);
        uint2 v1 = __ldg(&hp[(size_t)s1 * 32 + lane]);
        uint2 v2 = __ldg(&hp[(size_t)s2 * 32 + lane]);
        uint2 v3 = __ldg(&hp[(size_t)s3 * 32 + lane]);
        float2 f;
        f = __half22float2(*(half2*)&v0.x); a0.x += f.x; a0.y += f.y;
        f = __half22float2(*(half2*)&v0.y); a0.z += f.x; a0.w += f.y;
        f = __half22float2(*(half2*)&v1.x); a1.x += f.x; a1.y += f.y;
        f = __half22float2(*(half2*)&v1.y); a1.z += f.x; a1.w += f.y;
        f = __half22float2(*(half2*)&v2.x); a2.x += f.x; a2.y += f.y;
        f = __half22float2(*(half2*)&v2.y); a2.z += f.x; a2.w += f.y;
        f = __half22float2(*(half2*)&v3.x); a3.x += f.x; a3.y += f.y;
        f = __half22float2(*(half2*)&v3.y); a3.z += f.x; a3.w += f.y;
    }
    for (; e < end; e++) {
        int s0 = __ldg(&g_csr[e]);
        uint2 v0 = __ldg(&hp[(size_t)s0 * 32 + lane]);
        float2 f;
        f = __half22float2(*(half2*)&v0.x); a0.x += f.x; a0.y += f.y;
        f = __half22float2(*(half2*)&v0.y); a0.z += f.x; a0.w += f.y;
    }
    float4 s4;
    s4.x = (a0.x + a1.x) + (a2.x + a3.x);
    s4.y = (a0.y + a1.y) + (a2.y + a3.y);
    s4.z = (a0.z + a1.z) + (a2.z + a3.z);
    s4.w = (a0.w + a1.w) + (a2.w + a3.w);

    half2 p0 = __float22half2_rn(make_float2(s4.x, s4.y));
    half2 p1 = __float22half2_rn(make_float2(s4.z, s4.w));
    unsigned idx = (unsigned)node * ROW_U32 + lane * 2;
    *(uint2*)&g_A16[idx] = make_uint2(*(unsigned*)&p0, *(unsigned*)&p1);
}

// ---------------------------------------------------------------------------
// Tensor-core GEMM: single-pass fp16 (m16n8k16 f32.f16.f16.f32),
// 64-row tile, 3 CTAs/SM (smem 52.7KB), scalar-LDS fragment loads.
// ---------------------------------------------------------------------------
#define SM_W 0
#define SM_A (SM_W + 128 * PADK * 2)          // 34816
#define SM_BIAS (SM_A + TM * PADK * 2)        // 52224
#define SM_TOTAL (SM_BIAS + 512)              // 52736

__device__ __forceinline__ void mma_fp16(float& c0, float& c1, float& c2, float& c3,
                                         unsigned a0, unsigned a1, unsigned a2, unsigned a3,
                                         unsigned b0, unsigned b1) {
    asm volatile(
        "mma.sync.aligned.m16n8k16.row.col.f32.f16.f16.f32 "
        "{%0,%1,%2,%3}, {%4,%5,%6,%7}, {%8,%9}, {%0,%1,%2,%3};"
        : "+f"(c0), "+f"(c1), "+f"(c2), "+f"(c3)
        : "r"(a0), "r"(a1), "r"(a2), "r"(a3), "r"(b0), "r"(b1));
}

__global__ void __launch_bounds__(256, 3)
k_gemm_mma(const float* __restrict__ bias,
           float* __restrict__ out, int M) {
    extern __shared__ char sm[];
    int tid = threadIdx.x;
    int wid = tid >> 5;
    int lane = tid & 31;
    int m0 = blockIdx.x * TM;

    if (tid < 128) *(float*)(sm + SM_BIAS + tid * 4) = bias[tid];

    // W image -> smem (coalesced uint4, L2-broadcast)
    {
        const uint4* sw = (const uint4*)g_W16;
        uint4* dw = (uint4*)(sm + SM_W);
        for (int i = tid; i < W_IMG_U32 / 4; i += 256) dw[i] = sw[i];
    }

    // A image -> smem: pure uint4 copy (1088 uint4)
    {
        const uint4* sa = (const uint4*)g_A16 + (size_t)m0 * (ROW_U32 / 4);
        uint4* da = (uint4*)(sm + SM_A);
#pragma unroll
        for (int j = 0; j < 5; j++) {
            int i = j * 256 + tid;
            if (i < TM * (ROW_U32 / 4)) da[i] = sa[i];
        }
    }
    __syncthreads();

    int wm = (wid & 3) * 16;
    int wn = (wid >> 2) * 64;
    int g = lane >> 2;
    int t = lane & 3;

    float acc[8][4];
#pragma unroll
    for (int nt = 0; nt < 8; nt++)
#pragma unroll
        for (int i = 0; i < 4; i++) acc[nt][i] = 0.f;

    const char* As = sm + SM_A;
    const char* Ws = sm + SM_W;
#pragma unroll
    for (int ks = 0; ks < 8; ks++) {
        int k0 = ks * 16;
        unsigned a[4];
        {
            unsigned base = (unsigned)((wm + g) * PADK + k0 + 2 * t) * 2;
            a[0] = *(const unsigned*)(As + base);
            a[1] = *(const unsigned*)(As + base + 8 * PADK * 2);
            a[2] = *(const unsigned*)(As + base + 16);
            a[3] = *(const unsigned*)(As + base + 8 * PADK * 2 + 16);
        }
        unsigned bb[8][2];
#pragma unroll
        for (int nt = 0; nt < 8; nt++) {
            unsigned base = (unsigned)((wn + nt * 8 + g) * PADK + k0 + 2 * t) * 2;
            bb[nt][0] = *(const unsigned*)(Ws + base);
            bb[nt][1] = *(const unsigned*)(Ws + base + 16);
        }
#pragma unroll
        for (int nt = 0; nt < 8; nt++)
            mma_fp16(acc[nt][0], acc[nt][1], acc[nt][2], acc[nt][3],
                     a[0], a[1], a[2], a[3], bb[nt][0], bb[nt][1]);
    }

    // epilogue: bias + relu + float2 stores
    {
        const float* bs = (const float*)(sm + SM_BIAS);
        int r0 = wm + g;
        int gm0 = m0 + r0;
        int gm1 = gm0 + 8;
#pragma unroll
        for (int nt = 0; nt < 8; nt++) {
            int c = wn + nt * 8 + 2 * t;
            float2 bv = *(const float2*)(bs + c);
            if (gm0 < M) {
                float2 o;
                o.x = fmaxf(acc[nt][0] + bv.x, 0.f);
                o.y = fmaxf(acc[nt][1] + bv.y, 0.f);
                *(float2*)(out + (size_t)gm0 * D + c) = o;
            }
            if (gm1 < M) {
                float2 o;
                o.x = fmaxf(acc[nt][2] + bv.x, 0.f);
                o.y = fmaxf(acc[nt][3] + bv.y, 0.f);
                *(float2*)(out + (size_t)gm1 * D + c) = o;
            }
        }
    }
}

// ---------------------------------------------------------------------------
// Launch
// ---------------------------------------------------------------------------
extern "C" void kernel_launch(void* const* d_in, const int* in_sizes, int n_in,
                              void* d_out, int out_size) {
    const float* h    = (const float*)d_in[0];
    const int*   esrc = (const int*)d_in[1];
    const int*   edst = (const int*)d_in[2];
    const float* W    = (const float*)d_in[3];
    const float* b    = (const float*)d_in[4];
    float* out = (float*)d_out;

    int M = in_sizes[0] / D;   // 100000
    int E = in_sizes[1];       // 1600000

    cudaFuncSetAttribute(k_gemm_mma, cudaFuncAttributeMaxDynamicSharedMemorySize,
                         SM_TOTAL);

    int nb = (M + 1023) / 1024;
    int zeroBlocks = (M + 255) / 256;          // 391
    int convBlocks = (M * 32 + 255) / 256;     // 12500

    k_init<<<32 + zeroBlocks + convBlocks, 256>>>(W, h, M, zeroBlocks);
    k_hist<<<1024, 256>>>(edst, E);
    k_scan1<<<nb, 256>>>(M);
    k_scan2<<<1, 256>>>(nb);
    k_scan3<<<(M + 255) / 256, 256>>>(M, E);
    k_fill<<<1024, 256>>>(esrc, edst, E);
    k_gather<<<(M + 7) / 8, 256>>>(M);
    k_gemm_mma<<<(M + TM - 1) / TM, 256, SM_TOTAL>>>(b, out, M);
}